// round 12
// baseline (speedup 1.0000x reference)
#include <cuda_runtime.h>
#include <cuda_bf16.h>
#include <cstdint>

#define Bsz 128
#define Ssz 512
#define Hsz 1024
#define NL  4
#define NPART 6
#define NST 3

// out layout: output [512,128,1024], state_h [4,128,1024], state_c [4,128,1024]
#define OUT_OFF_H ((size_t)512 * 128 * 1024)
#define OUT_OFF_C (OUT_OFF_H + (size_t)4 * 128 * 1024)

// ---------------- scratch (__device__ globals; no allocations allowed) ------
__device__ int      d_len[Bsz];
__device__ int      d_sorted[Bsz];
__device__ int      d_unsort[Bsz];
__device__ int      d_bslast;
__device__ unsigned d_xbh[2][Hsz / 2][Bsz];    // packed bf16x2 hi of x^T: [kpair][r]
__device__ unsigned d_xbl[2][Hsz / 2][Bsz];    // packed bf16x2 lo residual
__device__ float    d_hfin[Bsz][Hsz];          // final top-layer h, row-major [r][hc]
__device__ float    d_G2[NPART][3 * Hsz][Bsz]; // split-K partials: [part][vm][r]

// pack two floats to bf16x2: low half = lo_val (k even), high half = hi_val (k odd)
__device__ __forceinline__ unsigned pack_bf16(float lo_val, float hi_val) {
    unsigned r;
    asm("cvt.rn.bf16x2.f32 %0, %1, %2;" : "=r"(r) : "f"(hi_val), "f"(lo_val));
    return r;
}
__device__ __forceinline__ float bf_lo(unsigned r) { return __uint_as_float(r << 16); }
__device__ __forceinline__ float bf_hi(unsigned r) { return __uint_as_float(r & 0xFFFF0000u); }
__device__ __forceinline__ void decomp2(float f0, float f1, unsigned& hi, unsigned& lo) {
    hi = pack_bf16(f0, f1);
    lo = pack_bf16(f0 - bf_lo(hi), f1 - bf_hi(hi));
}

// ------- kernel 1: fused lengths + stable descending argsort (1 CTA) --------
__global__ void __launch_bounds__(512) k_lensort(const int* __restrict__ x) {
    __shared__ int sl[Bsz];
    int t = threadIdx.x, w = t >> 5, lane = t & 31;
    #pragma unroll
    for (int rd = 0; rd < 8; rd++) {
        int b = rd * 16 + w;
        int cnt = 0;
        #pragma unroll
        for (int k = 0; k < 16; k++) cnt += (x[b * Ssz + k * 32 + lane] > 0);
        #pragma unroll
        for (int o = 16; o; o >>= 1) cnt += __shfl_down_sync(0xFFFFFFFFu, cnt, o);
        if (lane == 0) sl[b] = cnt;
    }
    __syncthreads();
    if (t < Bsz) {
        int li = sl[t];
        int rank = 0, c512 = 0;
        #pragma unroll 8
        for (int j = 0; j < Bsz; j++) {
            int lj = sl[j];
            rank += (lj > li) || (lj == li && j < t);
            c512 += (lj >= Ssz);
        }
        d_len[t] = li;
        d_unsort[t] = rank;
        d_sorted[rank] = t;
        if (t == 0) d_bslast = c512;
    }
}

// ------- kernel 2: xb{h,l}[0][kp][r] = bf16 decomposition of emb row --------
__global__ void k_gather(const int* __restrict__ x, const float* __restrict__ emb) {
    int r = blockIdx.x;
    int tok = x[d_sorted[r] * Ssz];  // t = 0
    const float2* src = (const float2*)(emb + (size_t)tok * Hsz);
    #pragma unroll
    for (int j = 0; j < 2; j++) {
        int kp = threadIdx.x + j * 256;     // pair index 0..511
        float2 f = src[kp];
        unsigned hi, lo;
        decomp2(f.x, f.y, hi, lo);
        d_xbh[0][kp][r] = hi;
        d_xbl[0][kp][r] = lo;
    }
}

// ---------------- kernel 3: 3x-bf16-split tensor-core GEMM ------------------
// R7 structure; bl-frag load deferred past term 2 to cut peak regs; 3 CTAs/SM.
#define ASTR 20    // 64 x 16 fp32 weight tile rows, padded stride
#define BSTR 136   // 8 x 128 uint tile (bf16x2 pairs), padded stride

__device__ __forceinline__ void mma16(float* c, const unsigned* a, const unsigned* b) {
    asm volatile(
        "mma.sync.aligned.m16n8k16.row.col.f32.bf16.bf16.f32 "
        "{%0,%1,%2,%3}, {%4,%5,%6,%7}, {%8,%9}, {%0,%1,%2,%3};"
        : "+f"(c[0]), "+f"(c[1]), "+f"(c[2]), "+f"(c[3])
        : "r"(a[0]), "r"(a[1]), "r"(a[2]), "r"(a[3]), "r"(b[0]), "r"(b[1]));
}
__device__ __forceinline__ void cpa16(unsigned s, const void* g) {
    asm volatile("cp.async.cg.shared.global [%0], [%1], 16;" :: "r"(s), "l"(g));
}

__global__ void __launch_bounds__(256, 3) k_gemm3(const float* __restrict__ W, int cur) {
    __shared__ __align__(16) float    As[NST][64 * ASTR];
    __shared__ __align__(16) unsigned Bh[NST][8 * BSTR];
    __shared__ __align__(16) unsigned Bl[NST][8 * BSTR];

    int tid  = threadIdx.x;
    int vm0  = blockIdx.x * 64;                // 0..3008
    int gate = vm0 >> 10;
    const float* A = W + (size_t)(vm0 + (gate > 0 ? 1024 : 0)) * Hsz;
    const unsigned* XH = &d_xbh[cur][0][0];
    const unsigned* XL = &d_xbl[cur][0][0];

    int part = blockIdx.y;
    int i0 = part * 64 / NPART, i1 = (part + 1) * 64 / NPART;  // BK=16 stages
    int niter = i1 - i0;

    unsigned asb[NST], bhb[NST], blb[NST];
    #pragma unroll
    for (int s = 0; s < NST; s++) {
        asb[s] = (unsigned)__cvta_generic_to_shared(&As[s][0]);
        bhb[s] = (unsigned)__cvta_generic_to_shared(&Bh[s][0]);
        blb[s] = (unsigned)__cvta_generic_to_shared(&Bl[s][0]);
    }

    int a_row = tid >> 2, a_seg = tid & 3;
    int b_kr  = tid >> 5, b_seg = tid & 31;
    unsigned a_soff = (unsigned)(a_row * ASTR + a_seg * 4) * 4;
    unsigned b_soff = (unsigned)(b_kr * BSTR + b_seg * 4) * 4;

    auto load_stage = [&](int buf, int iter) {
        int kw  = iter * 16;   // float k base
        int kp0 = iter * 8;    // pair base
        cpa16(asb[buf] + a_soff, A + (size_t)a_row * Hsz + kw + a_seg * 4);
        cpa16(bhb[buf] + b_soff, XH + (size_t)(kp0 + b_kr) * Bsz + b_seg * 4);
        cpa16(blb[buf] + b_soff, XL + (size_t)(kp0 + b_kr) * Bsz + b_seg * 4);
    };

    int lane = tid & 31, wid = tid >> 5;
    int wm = (wid & 3) * 16;      // 4 warps over 64 gate cols
    int wn = (wid >> 2) * 64;     // 2 warps over 128 batch rows
    int g  = lane >> 2, tg = lane & 3;

    float acc[8][4];
    #pragma unroll
    for (int b = 0; b < 8; b++)
        #pragma unroll
        for (int cx = 0; cx < 4; cx++) acc[b][cx] = 0.f;

    load_stage(0, i0);
    asm volatile("cp.async.commit_group;" ::: "memory");
    if (niter > 1) load_stage(1, i0 + 1);
    asm volatile("cp.async.commit_group;" ::: "memory");

    for (int it = 0; it < niter; ++it) {
        asm volatile("cp.async.wait_group 1;" ::: "memory");
        __syncthreads();

        if (it + 2 < niter) load_stage((it + 2) % NST, i0 + it + 2);
        asm volatile("cp.async.commit_group;" ::: "memory");

        int buf = it % NST;
        const float*    As_ = &As[buf][0];
        const unsigned* Bh_ = &Bh[buf][0];
        const unsigned* Bl_ = &Bl[buf][0];

        // A fragments (decomp overlaps B LDS latency)
        unsigned ah[4], al[4];
        {
            int row0 = wm + g;
            int row1 = row0 + 8;
            float2 f0 = *(const float2*)&As_[row0 * ASTR + 2 * tg];
            float2 f1 = *(const float2*)&As_[row1 * ASTR + 2 * tg];
            float2 f2 = *(const float2*)&As_[row0 * ASTR + 2 * tg + 8];
            float2 f3 = *(const float2*)&As_[row1 * ASTR + 2 * tg + 8];
            decomp2(f0.x, f0.y, ah[0], al[0]);
            decomp2(f1.x, f1.y, ah[1], al[1]);
            decomp2(f2.x, f2.y, ah[2], al[2]);
            decomp2(f3.x, f3.y, ah[3], al[3]);
        }

        // B hi fragments
        unsigned bh[8][2];
        #pragma unroll
        for (int nf = 0; nf < 8; nf++) {
            int n = wn + nf * 8 + g;
            bh[nf][0] = Bh_[tg * BSTR + n];
            bh[nf][1] = Bh_[(tg + 4) * BSTR + n];
        }

        // terms 1+2 (al dies after term 2)
        #pragma unroll
        for (int nf = 0; nf < 8; nf++) mma16(acc[nf], ah, bh[nf]);
        #pragma unroll
        for (int nf = 0; nf < 8; nf++) mma16(acc[nf], al, bh[nf]);

        // B lo fragments loaded late (after al is dead) to cut peak regs
        unsigned bl[8][2];
        #pragma unroll
        for (int nf = 0; nf < 8; nf++) {
            int n = wn + nf * 8 + g;
            bl[nf][0] = Bl_[tg * BSTR + n];
            bl[nf][1] = Bl_[(tg + 4) * BSTR + n];
        }
        #pragma unroll
        for (int nf = 0; nf < 8; nf++) mma16(acc[nf], ah, bl[nf]);
    }

    float* Gp = &d_G2[part][0][0];
    int m0 = vm0 + wm + g;
    #pragma unroll
    for (int nf = 0; nf < 8; nf++) {
        int n0 = wn + nf * 8 + tg * 2;
        *(float2*)(Gp + (size_t)m0 * Bsz + n0) =
            make_float2(acc[nf][0], acc[nf][1]);
        *(float2*)(Gp + (size_t)(m0 + 8) * Bsz + n0) =
            make_float2(acc[nf][2], acc[nf][3]);
    }
}

// ---------------- kernel 4: split-K reduce + LSTM activations ---------------
// 512 CTAs x 128 threads: 4 hc-pairs x 32 r per block, 1 task/thread.
__device__ __forceinline__ float tanha(float x) {
    float r; asm("tanh.approx.f32 %0, %1;" : "=f"(r) : "f"(x)); return r;
}
__device__ __forceinline__ float sigf(float x) {
    return fmaf(tanha(0.5f * x), 0.5f, 0.5f);
}

__global__ void __launch_bounds__(128) k_act5(const float* __restrict__ bih,
                                              const float* __restrict__ bhh,
                                              int l, int nxt, float* __restrict__ out) {
    __shared__ float sh[8][33], sc[8][33];
    int tid = threadIdx.x;
    int hb = blockIdx.x * 8;         // 128 hc-groups of 8
    int rb = blockIdx.y * 32;        // 4 r-groups of 32
    int bsl = d_bslast;

    // phase 1: one (hc-pair, r) task per thread; 36 independent coalesced loads
    {
        int pl = tid >> 5;            // 0..3 local hc pair
        int rl = tid & 31;
        int r  = rb + rl;
        int hc0 = hb + 2 * pl;
        float hh2[2];
        #pragma unroll
        for (int e = 0; e < 2; e++) {
            int hc = hc0 + e;
            float gi = 0.f, gg = 0.f, go = 0.f;
            #pragma unroll
            for (int p = 0; p < NPART; p++) {
                gi += d_G2[p][hc][r];
                gg += d_G2[p][Hsz + hc][r];
                go += d_G2[p][2 * Hsz + hc][r];
            }
            gi += bih[hc] + bhh[hc];
            gg += bih[2 * Hsz + hc] + bhh[2 * Hsz + hc];
            go += bih[3 * Hsz + hc] + bhh[3 * Hsz + hc];
            float cc = sigf(gi) * tanha(gg);
            float hh = sigf(go) * tanha(cc);
            hh2[e] = hh;
            sh[2 * pl + e][rl] = hh;
            sc[2 * pl + e][rl] = cc;
        }
        unsigned hi, lo;
        decomp2(hh2[0], hh2[1], hi, lo);
        d_xbh[nxt][(hb >> 1) + pl][r] = hi;    // unmasked h feeds next layer
        d_xbl[nxt][(hb >> 1) + pl][r] = lo;
    }
    __syncthreads();
    // phase 2: masked state writes + final-h copy, hc-contiguous (8 hc x 32 r)
    #pragma unroll
    for (int w = 0; w < 2; w++) {
        int idx = w * 128 + tid;       // 0..255
        int rl = idx >> 3, hcl = idx & 7;
        int r = rb + rl;
        float m = (r < bsl) ? 1.f : 0.f;
        size_t o = ((size_t)(l * Bsz + r) << 10) + hb + hcl;
        float hh = sh[hcl][rl];
        out[OUT_OFF_H + o] = hh * m;
        out[OUT_OFF_C + o] = sc[hcl][rl] * m;
        d_hfin[r][hb + hcl] = hh;      // row-major final h (last layer wins)
    }
}

// ---------------- kernel 5: output[t,b,:] = (t < len[b]) * h_top[b,:] -------
__global__ void k_output(float* __restrict__ out) {
    int b  = blockIdx.x;
    int tb = blockIdx.y * 64;
    int len = d_len[b];
    int rk  = d_unsort[b];
    float4 hv = *(const float4*)&d_hfin[rk][threadIdx.x * 4];
    float4 z  = make_float4(0.f, 0.f, 0.f, 0.f);
    size_t col = (size_t)threadIdx.x * 4;
    #pragma unroll 4
    for (int t = tb; t < tb + 64; t++) {
        float4 v = (t < len) ? hv : z;
        __stcs((float4*)&out[(((size_t)t * Bsz) + b) * Hsz + col], v);
    }
}

// ---------------- launch -----------------------------------------------------
extern "C" void kernel_launch(void* const* d_in, const int* in_sizes, int n_in,
                              void* d_out, int out_size) {
    const int*   x    = (const int*)d_in[0];
    const float* emb  = (const float*)d_in[1];
    const float* W_ih = (const float*)d_in[2];
    // d_in[3] = W_hh: unused (h0 == 0)
    const float* b_ih = (const float*)d_in[4];
    const float* b_hh = (const float*)d_in[5];
    float* out = (float*)d_out;

    k_lensort<<<1, 512>>>(x);
    k_gather<<<Bsz, 256>>>(x, emb);
    for (int l = 0; l < NL; l++) {
        int cur = l & 1;
        k_gemm3<<<dim3(48, NPART), 256>>>(W_ih + (size_t)l * 4 * Hsz * Hsz, cur);
        k_act5<<<dim3(128, 4), 128>>>(b_ih + (size_t)l * 4 * Hsz, b_hh + (size_t)l * 4 * Hsz,
                                      l, cur ^ 1, out);
    }
    k_output<<<dim3(Bsz, 8), 256>>>(out);
}

// round 13
// speedup vs baseline: 1.0375x; 1.0375x over previous
#include <cuda_runtime.h>
#include <cuda_bf16.h>
#include <cstdint>

#define Bsz 128
#define Ssz 512
#define Hsz 1024
#define NL  4
#define NPART 6
#define NST 3

// out layout: output [512,128,1024], state_h [4,128,1024], state_c [4,128,1024]
#define OUT_OFF_H ((size_t)512 * 128 * 1024)
#define OUT_OFF_C (OUT_OFF_H + (size_t)4 * 128 * 1024)

// ---------------- scratch (__device__ globals; no allocations allowed) ------
__device__ int      d_len[Bsz];
__device__ int      d_sorted[Bsz];
__device__ int      d_unsort[Bsz];
__device__ int      d_bslast;
__device__ unsigned d_xbh[2][Hsz / 2][Bsz];    // packed bf16x2 hi of x^T: [kpair][r]
__device__ unsigned d_xbl[2][Hsz / 2][Bsz];    // packed bf16x2 lo residual
__device__ float    d_hfin[Bsz][Hsz];          // final top-layer h, row-major [r][hc]
__device__ float    d_G2[NPART][3 * Hsz][Bsz]; // split-K partials: [part][vm][r]

// pack two floats to bf16x2: low half = lo_val (k even), high half = hi_val (k odd)
__device__ __forceinline__ unsigned pack_bf16(float lo_val, float hi_val) {
    unsigned r;
    asm("cvt.rn.bf16x2.f32 %0, %1, %2;" : "=r"(r) : "f"(hi_val), "f"(lo_val));
    return r;
}
__device__ __forceinline__ float bf_lo(unsigned r) { return __uint_as_float(r << 16); }
__device__ __forceinline__ float bf_hi(unsigned r) { return __uint_as_float(r & 0xFFFF0000u); }
__device__ __forceinline__ void decomp2(float f0, float f1, unsigned& hi, unsigned& lo) {
    hi = pack_bf16(f0, f1);
    lo = pack_bf16(f0 - bf_lo(hi), f1 - bf_hi(hi));
}

// ------- kernel 1: fused lengths + stable descending argsort (1 CTA) --------
__global__ void __launch_bounds__(512) k_lensort(const int* __restrict__ x) {
    __shared__ int sl[Bsz];
    int t = threadIdx.x, w = t >> 5, lane = t & 31;
    #pragma unroll
    for (int rd = 0; rd < 8; rd++) {
        int b = rd * 16 + w;
        int cnt = 0;
        #pragma unroll
        for (int k = 0; k < 16; k++) cnt += (x[b * Ssz + k * 32 + lane] > 0);
        #pragma unroll
        for (int o = 16; o; o >>= 1) cnt += __shfl_down_sync(0xFFFFFFFFu, cnt, o);
        if (lane == 0) sl[b] = cnt;
    }
    __syncthreads();
    if (t < Bsz) {
        int li = sl[t];
        int rank = 0, c512 = 0;
        #pragma unroll 8
        for (int j = 0; j < Bsz; j++) {
            int lj = sl[j];
            rank += (lj > li) || (lj == li && j < t);
            c512 += (lj >= Ssz);
        }
        d_len[t] = li;
        d_unsort[t] = rank;
        d_sorted[rank] = t;
        if (t == 0) d_bslast = c512;
    }
}

// ------- kernel 2: xb{h,l}[0][kp][r] = bf16 decomposition of emb row --------
__global__ void k_gather(const int* __restrict__ x, const float* __restrict__ emb) {
    int r = blockIdx.x;
    int tok = x[d_sorted[r] * Ssz];  // t = 0
    const float2* src = (const float2*)(emb + (size_t)tok * Hsz);
    #pragma unroll
    for (int j = 0; j < 2; j++) {
        int kp = threadIdx.x + j * 256;     // pair index 0..511
        float2 f = src[kp];
        unsigned hi, lo;
        decomp2(f.x, f.y, hi, lo);
        d_xbh[0][kp][r] = hi;
        d_xbl[0][kp][r] = lo;
    }
}

// ---------------- kernel 3: 3x-bf16-split tensor-core GEMM ------------------
// (R7/R11 kernel verbatim — best measured configuration.)
#define ASTR 20    // 64 x 16 fp32 weight tile rows, padded stride
#define BSTR 136   // 8 x 128 uint tile (bf16x2 pairs), padded stride

__device__ __forceinline__ void mma16(float* c, const unsigned* a, const unsigned* b) {
    asm volatile(
        "mma.sync.aligned.m16n8k16.row.col.f32.bf16.bf16.f32 "
        "{%0,%1,%2,%3}, {%4,%5,%6,%7}, {%8,%9}, {%0,%1,%2,%3};"
        : "+f"(c[0]), "+f"(c[1]), "+f"(c[2]), "+f"(c[3])
        : "r"(a[0]), "r"(a[1]), "r"(a[2]), "r"(a[3]), "r"(b[0]), "r"(b[1]));
}
__device__ __forceinline__ void cpa16(unsigned s, const void* g) {
    asm volatile("cp.async.cg.shared.global [%0], [%1], 16;" :: "r"(s), "l"(g));
}

__global__ void __launch_bounds__(256, 2) k_gemm3(const float* __restrict__ W, int cur) {
    __shared__ __align__(16) float    As[NST][64 * ASTR];
    __shared__ __align__(16) unsigned Bh[NST][8 * BSTR];
    __shared__ __align__(16) unsigned Bl[NST][8 * BSTR];

    int tid  = threadIdx.x;
    int vm0  = blockIdx.x * 64;                // 0..3008
    int gate = vm0 >> 10;
    const float* A = W + (size_t)(vm0 + (gate > 0 ? 1024 : 0)) * Hsz;
    const unsigned* XH = &d_xbh[cur][0][0];
    const unsigned* XL = &d_xbl[cur][0][0];

    int part = blockIdx.y;
    int i0 = part * 64 / NPART, i1 = (part + 1) * 64 / NPART;  // BK=16 stages
    int niter = i1 - i0;

    unsigned asb[NST], bhb[NST], blb[NST];
    #pragma unroll
    for (int s = 0; s < NST; s++) {
        asb[s] = (unsigned)__cvta_generic_to_shared(&As[s][0]);
        bhb[s] = (unsigned)__cvta_generic_to_shared(&Bh[s][0]);
        blb[s] = (unsigned)__cvta_generic_to_shared(&Bl[s][0]);
    }

    int a_row = tid >> 2, a_seg = tid & 3;
    int b_kr  = tid >> 5, b_seg = tid & 31;
    unsigned a_soff = (unsigned)(a_row * ASTR + a_seg * 4) * 4;
    unsigned b_soff = (unsigned)(b_kr * BSTR + b_seg * 4) * 4;

    auto load_stage = [&](int buf, int iter) {
        int kw  = iter * 16;   // float k base
        int kp0 = iter * 8;    // pair base
        cpa16(asb[buf] + a_soff, A + (size_t)a_row * Hsz + kw + a_seg * 4);
        cpa16(bhb[buf] + b_soff, XH + (size_t)(kp0 + b_kr) * Bsz + b_seg * 4);
        cpa16(blb[buf] + b_soff, XL + (size_t)(kp0 + b_kr) * Bsz + b_seg * 4);
    };

    int lane = tid & 31, wid = tid >> 5;
    int wm = (wid & 3) * 16;      // 4 warps over 64 gate cols
    int wn = (wid >> 2) * 64;     // 2 warps over 128 batch rows
    int g  = lane >> 2, tg = lane & 3;

    float acc[8][4];
    #pragma unroll
    for (int b = 0; b < 8; b++)
        #pragma unroll
        for (int cx = 0; cx < 4; cx++) acc[b][cx] = 0.f;

    load_stage(0, i0);
    asm volatile("cp.async.commit_group;" ::: "memory");
    if (niter > 1) load_stage(1, i0 + 1);
    asm volatile("cp.async.commit_group;" ::: "memory");

    for (int it = 0; it < niter; ++it) {
        asm volatile("cp.async.wait_group 1;" ::: "memory");
        __syncthreads();

        if (it + 2 < niter) load_stage((it + 2) % NST, i0 + it + 2);
        asm volatile("cp.async.commit_group;" ::: "memory");

        int buf = it % NST;
        const float*    As_ = &As[buf][0];
        const unsigned* Bh_ = &Bh[buf][0];
        const unsigned* Bl_ = &Bl[buf][0];

        unsigned ah[4], al[4];
        {
            int row0 = wm + g;
            int row1 = row0 + 8;
            float2 f0 = *(const float2*)&As_[row0 * ASTR + 2 * tg];
            float2 f1 = *(const float2*)&As_[row1 * ASTR + 2 * tg];
            float2 f2 = *(const float2*)&As_[row0 * ASTR + 2 * tg + 8];
            float2 f3 = *(const float2*)&As_[row1 * ASTR + 2 * tg + 8];
            decomp2(f0.x, f0.y, ah[0], al[0]);
            decomp2(f1.x, f1.y, ah[1], al[1]);
            decomp2(f2.x, f2.y, ah[2], al[2]);
            decomp2(f3.x, f3.y, ah[3], al[3]);
        }

        unsigned bh[8][2], bl[8][2];
        #pragma unroll
        for (int nf = 0; nf < 8; nf++) {
            int n = wn + nf * 8 + g;
            bh[nf][0] = Bh_[tg * BSTR + n];
            bh[nf][1] = Bh_[(tg + 4) * BSTR + n];
            bl[nf][0] = Bl_[tg * BSTR + n];
            bl[nf][1] = Bl_[(tg + 4) * BSTR + n];
        }

        #pragma unroll
        for (int nf = 0; nf < 8; nf++) mma16(acc[nf], ah, bh[nf]);
        #pragma unroll
        for (int nf = 0; nf < 8; nf++) mma16(acc[nf], al, bh[nf]);
        #pragma unroll
        for (int nf = 0; nf < 8; nf++) mma16(acc[nf], ah, bl[nf]);
    }

    float* Gp = &d_G2[part][0][0];
    int m0 = vm0 + wm + g;
    #pragma unroll
    for (int nf = 0; nf < 8; nf++) {
        int n0 = wn + nf * 8 + tg * 2;
        *(float2*)(Gp + (size_t)m0 * Bsz + n0) =
            make_float2(acc[nf][0], acc[nf][1]);
        *(float2*)(Gp + (size_t)(m0 + 8) * Bsz + n0) =
            make_float2(acc[nf][2], acc[nf][3]);
    }
}

// ---------------- kernel 4: split-K reduce + LSTM activations ---------------
// ONE cell per thread: 1024 CTAs x 128 thr -> ~28 warps/SM of latency hiding.
// 18 partial loads forced into an array so ptxas batches them (MLP=18).
__device__ __forceinline__ float tanha(float x) {
    float r; asm("tanh.approx.f32 %0, %1;" : "=f"(r) : "f"(x)); return r;
}
__device__ __forceinline__ float sigf(float x) {
    return fmaf(tanha(0.5f * x), 0.5f, 0.5f);
}

__global__ void __launch_bounds__(128) k_act6(const float* __restrict__ bih,
                                              const float* __restrict__ bhh,
                                              int l, int nxt, float* __restrict__ out) {
    __shared__ float sh[8][17], sc[8][17];
    int tid = threadIdx.x;
    int hb = blockIdx.x * 8;         // 128 hc-groups of 8
    int rb = blockIdx.y * 16;        // 8 r-groups of 16
    int bsl = d_bslast;

    // phase 1: one (hc, r) cell per thread
    int hcl = tid >> 4;               // 0..7
    int rl  = tid & 15;
    int hc  = hb + hcl;
    int r   = rb + rl;
    {
        float v[18];
        #pragma unroll
        for (int p = 0; p < NPART; p++) {
            v[p]      = d_G2[p][hc][r];
            v[6 + p]  = d_G2[p][Hsz + hc][r];
            v[12 + p] = d_G2[p][2 * Hsz + hc][r];
        }
        float gi = ((v[0] + v[1]) + (v[2] + v[3])) + (v[4] + v[5])
                 + bih[hc] + bhh[hc];
        float gg = ((v[6] + v[7]) + (v[8] + v[9])) + (v[10] + v[11])
                 + bih[2 * Hsz + hc] + bhh[2 * Hsz + hc];
        float go = ((v[12] + v[13]) + (v[14] + v[15])) + (v[16] + v[17])
                 + bih[3 * Hsz + hc] + bhh[3 * Hsz + hc];
        float cc = sigf(gi) * tanha(gg);
        float hh = sigf(go) * tanha(cc);
        sh[hcl][rl] = hh;
        sc[hcl][rl] = cc;
        // masked state + final-h writes (hc index varies fastest across lanes
        // within the 16-thread half: write here per-thread, r-major layout)
        float m = (r < bsl) ? 1.f : 0.f;
        size_t o = ((size_t)(l * Bsz + r) << 10) + hc;
        out[OUT_OFF_H + o] = hh * m;
        out[OUT_OFF_C + o] = cc * m;
        d_hfin[r][hc] = hh;
    }
    __syncthreads();
    // phase 2: bf16x2 pair packing for next layer (threads 0..63)
    if (tid < 64) {
        int pl  = tid >> 4;            // 0..3 local pair
        int rl2 = tid & 15;
        int r2  = rb + rl2;
        unsigned hi, lo;
        decomp2(sh[2 * pl][rl2], sh[2 * pl + 1][rl2], hi, lo);
        d_xbh[nxt][(hb >> 1) + pl][r2] = hi;
        d_xbl[nxt][(hb >> 1) + pl][r2] = lo;
    }
}

// ---------------- kernel 5: output[t,b,:] = (t < len[b]) * h_top[b,:] -------
__global__ void k_output(float* __restrict__ out) {
    int b  = blockIdx.x;
    int tb = blockIdx.y * 64;
    int len = d_len[b];
    int rk  = d_unsort[b];
    float4 hv = *(const float4*)&d_hfin[rk][threadIdx.x * 4];
    float4 z  = make_float4(0.f, 0.f, 0.f, 0.f);
    size_t col = (size_t)threadIdx.x * 4;
    #pragma unroll 4
    for (int t = tb; t < tb + 64; t++) {
        float4 v = (t < len) ? hv : z;
        __stcs((float4*)&out[(((size_t)t * Bsz) + b) * Hsz + col], v);
    }
}

// ---------------- launch -----------------------------------------------------
extern "C" void kernel_launch(void* const* d_in, const int* in_sizes, int n_in,
                              void* d_out, int out_size) {
    const int*   x    = (const int*)d_in[0];
    const float* emb  = (const float*)d_in[1];
    const float* W_ih = (const float*)d_in[2];
    // d_in[3] = W_hh: unused (h0 == 0)
    const float* b_ih = (const float*)d_in[4];
    const float* b_hh = (const float*)d_in[5];
    float* out = (float*)d_out;

    k_lensort<<<1, 512>>>(x);
    k_gather<<<Bsz, 256>>>(x, emb);
    for (int l = 0; l < NL; l++) {
        int cur = l & 1;
        k_gemm3<<<dim3(48, NPART), 256>>>(W_ih + (size_t)l * 4 * Hsz * Hsz, cur);
        k_act6<<<dim3(128, 8), 128>>>(b_ih + (size_t)l * 4 * Hsz, b_hh + (size_t)l * 4 * Hsz,
                                      l, cur ^ 1, out);
    }
    k_output<<<dim3(Bsz, 8), 256>>>(out);
}